// round 3
// baseline (speedup 1.0000x reference)
#include <cuda_runtime.h>
#include <cstdint>
#include <math.h>

// ---------------------------------------------------------------------------
// Problem constants
// ---------------------------------------------------------------------------
static constexpr int Bn = 32;
static constexpr int Sn = 1024;
static constexpr int En = 512;
static constexpr int Hn = 8;
static constexpr int Dn = 64;       // E / H
static constexpr int Ln = 2;
static constexpr int Mn = Bn * Sn;  // 32768 rows
static constexpr size_t ME = (size_t)Mn * En;  // 16,777,216 elements
static constexpr size_t WSZ = (size_t)En * En; // 262144 per weight matrix

// Scratch: X, Q, K, V, Attn (5 * 64MB) + PE (2MB) + transposed weights (8MB)
__device__ float g_buf[5 * ME + (size_t)Sn * En + 4 * Ln * WSZ];

// ---------------------------------------------------------------------------
// Helpers
// ---------------------------------------------------------------------------
__device__ __forceinline__ uint32_t f2tf32(float f) {
    uint32_t r;
    asm("cvt.rna.tf32.f32 %0, %1;" : "=r"(r) : "f"(f));
    return r;
}
__device__ __forceinline__ void cp16(uint32_t s, const void* g) {
    asm volatile("cp.async.cg.shared.global [%0], [%1], 16;" :: "r"(s), "l"(g));
}
__device__ __forceinline__ uint32_t smem_u32(const void* p) {
    uint32_t a;
    asm("{ .reg .u64 t; cvta.to.shared.u64 t, %1; cvt.u32.u64 %0, t; }" : "=r"(a) : "l"(p));
    return a;
}
__device__ __forceinline__ void mma_tf32(float* c, const uint32_t* a, const uint32_t* b) {
    asm volatile(
        "mma.sync.aligned.m16n8k8.row.col.f32.tf32.tf32.f32 "
        "{%0,%1,%2,%3}, {%4,%5,%6,%7}, {%8,%9}, {%0,%1,%2,%3};"
        : "+f"(c[0]), "+f"(c[1]), "+f"(c[2]), "+f"(c[3])
        : "r"(a[0]), "r"(a[1]), "r"(a[2]), "r"(a[3]), "r"(b[0]), "r"(b[1]));
}

// ---------------------------------------------------------------------------
// PE table
// ---------------------------------------------------------------------------
__global__ void pe_kernel(float* __restrict__ pe) {
    int idx = blockIdx.x * blockDim.x + threadIdx.x;
    if (idx >= Sn * En) return;
    int s = idx >> 9;
    int e = idx & 511;
    float i2 = (float)(e & ~1);
    float div = __expf(i2 * (-9.210340371976184f / (float)En));
    float a = (float)s * div;
    pe[idx] = (e & 1) ? cosf(a) : sinf(a);
}

// ---------------------------------------------------------------------------
// Embedding gather + PE add
// ---------------------------------------------------------------------------
__global__ void embed_kernel(const int* __restrict__ tok,
                             const float* __restrict__ table,
                             const float* __restrict__ pe,
                             float* __restrict__ x) {
    int idx4 = blockIdx.x * blockDim.x + threadIdx.x;
    if (idx4 >= Mn * (En / 4)) return;
    int row = idx4 >> 7;
    int d4  = idx4 & 127;
    int s   = row & (Sn - 1);
    int t   = tok[row];
    float4 tv = ((const float4*)table)[(size_t)t * 128 + d4];
    float4 pv = ((const float4*)pe)[(size_t)s * 128 + d4];
    float4 o;
    o.x = tv.x + pv.x; o.y = tv.y + pv.y; o.z = tv.z + pv.z; o.w = tv.w + pv.w;
    ((float4*)x)[idx4] = o;
}

// ---------------------------------------------------------------------------
// 512x512 transpose (per-layer weights): WT[n][k] = W[k][n]
// ---------------------------------------------------------------------------
__global__ void transpose512(const float* __restrict__ W, float* __restrict__ WT) {
    __shared__ float t[32][33];
    const float* w = W + (size_t)blockIdx.z * WSZ;
    float* wt = WT + (size_t)blockIdx.z * WSZ;
    int x0 = blockIdx.x * 32, y0 = blockIdx.y * 32;
#pragma unroll
    for (int i = threadIdx.y; i < 32; i += 8)
        t[i][threadIdx.x] = w[(size_t)(y0 + i) * En + x0 + threadIdx.x];
    __syncthreads();
#pragma unroll
    for (int i = threadIdx.y; i < 32; i += 8)
        wt[(size_t)(x0 + i) * En + y0 + threadIdx.x] = t[threadIdx.x][i];
}

// ---------------------------------------------------------------------------
// tf32 mma.sync GEMM: C[M,512] = A[M,512] @ W[512,512] + bias
// B operand = WT[n][k] (pre-transposed). CTA tile 128x128, 8 warps of 64x32.
// K chunked at 32, cp.async double-buffered. Smem rows padded to 36 floats
// (bank-conflict-free fragment loads: (m*36+k) mod 32 is a lane bijection).
// ---------------------------------------------------------------------------
static constexpr int KC = 32;                       // K per chunk
static constexpr int NCHUNK = En / KC;              // 16
static constexpr int PAD = 36;                      // padded row (floats)
static constexpr int TSZ = 128 * PAD;               // floats per tile (A or B)
static constexpr int BUFSZ = 2 * TSZ;               // A+B per buffer
static constexpr int SMEM_GEMM = 2 * BUFSZ * 4;     // 73728 bytes

template <bool RELU_RES>
__global__ __launch_bounds__(256)
void gemm_mma(const float* __restrict__ A, const float* __restrict__ BT,
              const float* __restrict__ bias, const float* __restrict__ res,
              float* __restrict__ C) {
    extern __shared__ float sm[];
    const uint32_t sb = smem_u32(sm);
    const int tid = threadIdx.x;
    const int col0 = blockIdx.x * 128;
    const int row0 = blockIdx.y * 128;
    const int wid = tid >> 5, lane = tid & 31;
    const int wy = wid >> 2, wx = wid & 3;          // 2x4 warp grid
    const int m_warp = wy * 64, n_warp = wx * 32;
    const int gid = lane >> 2, tg = lane & 3;

    float acc[4][4][4];
#pragma unroll
    for (int mt = 0; mt < 4; ++mt)
#pragma unroll
        for (int nt = 0; nt < 4; ++nt)
#pragma unroll
            for (int r = 0; r < 4; ++r) acc[mt][nt][r] = 0.f;

    auto load_chunk = [&](int c, int buf) {
        uint32_t abase = sb + buf * BUFSZ * 4;
        uint32_t bbase = abase + TSZ * 4;
        const float* Ag = A + (size_t)row0 * En + c * KC;
        const float* Bg = BT + (size_t)col0 * En + c * KC;
#pragma unroll
        for (int i = 0; i < 4; ++i) {               // 1024 float4 for A
            int idx = tid + i * 256;
            int m = idx >> 3, k4 = idx & 7;
            cp16(abase + (m * PAD + k4 * 4) * 4, Ag + (size_t)m * En + k4 * 4);
        }
#pragma unroll
        for (int i = 0; i < 4; ++i) {               // 1024 float4 for B
            int idx = tid + i * 256;
            int n = idx >> 3, k4 = idx & 7;
            cp16(bbase + (n * PAD + k4 * 4) * 4, Bg + (size_t)n * En + k4 * 4);
        }
        asm volatile("cp.async.commit_group;");
    };

    load_chunk(0, 0);
    for (int c = 0; c < NCHUNK; ++c) {
        if (c + 1 < NCHUNK) {
            load_chunk(c + 1, (c + 1) & 1);
            asm volatile("cp.async.wait_group 1;");
        } else {
            asm volatile("cp.async.wait_group 0;");
        }
        __syncthreads();

        const float* as_ = sm + (c & 1) * BUFSZ;
        const float* bs_ = as_ + TSZ;
#pragma unroll
        for (int ks = 0; ks < 4; ++ks) {
            const int k0 = ks * 8;
            uint32_t a[4][4], b[4][2];
#pragma unroll
            for (int mt = 0; mt < 4; ++mt) {
                int m = m_warp + mt * 16 + gid;
                a[mt][0] = f2tf32(as_[m * PAD + k0 + tg]);
                a[mt][1] = f2tf32(as_[(m + 8) * PAD + k0 + tg]);
                a[mt][2] = f2tf32(as_[m * PAD + k0 + tg + 4]);
                a[mt][3] = f2tf32(as_[(m + 8) * PAD + k0 + tg + 4]);
            }
#pragma unroll
            for (int nt = 0; nt < 4; ++nt) {
                int n = n_warp + nt * 8 + gid;
                b[nt][0] = f2tf32(bs_[n * PAD + k0 + tg]);
                b[nt][1] = f2tf32(bs_[n * PAD + k0 + tg + 4]);
            }
#pragma unroll
            for (int mt = 0; mt < 4; ++mt)
#pragma unroll
                for (int nt = 0; nt < 4; ++nt)
                    mma_tf32(acc[mt][nt], a[mt], b[nt]);
        }
        __syncthreads();
    }

    // Epilogue: thread owns (row gid / gid+8, cols 2*tg..2*tg+1) per 16x8 tile.
#pragma unroll
    for (int mt = 0; mt < 4; ++mt) {
#pragma unroll
        for (int nt = 0; nt < 4; ++nt) {
            int r0 = row0 + m_warp + mt * 16 + gid;
            int cc = col0 + n_warp + nt * 8 + tg * 2;
            float bx = bias[cc], by = bias[cc + 1];
            float2 v0, v1;
            v0.x = acc[mt][nt][0] + bx; v0.y = acc[mt][nt][1] + by;
            v1.x = acc[mt][nt][2] + bx; v1.y = acc[mt][nt][3] + by;
            size_t o0 = (size_t)r0 * En + cc;
            size_t o1 = (size_t)(r0 + 8) * En + cc;
            if (RELU_RES) {
                float2 q0 = *(const float2*)&res[o0];
                float2 q1 = *(const float2*)&res[o1];
                v0.x = q0.x + fmaxf(v0.x, 0.f); v0.y = q0.y + fmaxf(v0.y, 0.f);
                v1.x = q1.x + fmaxf(v1.x, 0.f); v1.y = q1.y + fmaxf(v1.y, 0.f);
            }
            *(float2*)&C[o0] = v0;
            *(float2*)&C[o1] = v1;
        }
    }
}

// ---------------------------------------------------------------------------
// Causal flash attention, fp32 SIMT (unchanged)
// ---------------------------------------------------------------------------
static constexpr int KT = 32;

__global__ __launch_bounds__(128)
void attn_kernel(const float* __restrict__ Q, const float* __restrict__ Kg,
                 const float* __restrict__ Vg, float* __restrict__ Og) {
    __shared__ float Ks[KT][64];
    __shared__ float Vs[KT][64];
    const int b = blockIdx.z, h = blockIdx.y, qt = blockIdx.x;
    const int r = threadIdx.x;
    const int qg = qt * 128 + r;

    const float4* qp = (const float4*)(Q + ((size_t)(b * Sn + qg)) * En + h * Dn);
    float4 q4[16];
#pragma unroll
    for (int i = 0; i < 16; ++i) q4[i] = qp[i];
    float4 o4[16];
#pragma unroll
    for (int i = 0; i < 16; ++i) o4[i] = make_float4(0.f, 0.f, 0.f, 0.f);

    float mi = -1e30f, l = 0.f;
    const int nkt = qt * 4 + 4;

    for (int kt = 0; kt < nkt; ++kt) {
        size_t base = ((size_t)(b * Sn + kt * KT)) * En + h * Dn;
#pragma unroll
        for (int i = 0; i < 4; ++i) {
            int idx = r + i * 128;
            int j  = idx >> 4;
            int d4 = idx & 15;
            ((float4*)Ks[j])[d4] = *(const float4*)(Kg + base + (size_t)j * En + d4 * 4);
            ((float4*)Vs[j])[d4] = *(const float4*)(Vg + base + (size_t)j * En + d4 * 4);
        }
        __syncthreads();

        float s[KT];
        float tmax = -1e30f;
        const int kbase = kt * KT;
#pragma unroll 4
        for (int j = 0; j < KT; ++j) {
            const float4* kr = (const float4*)Ks[j];
            float sj = 0.f;
#pragma unroll
            for (int d = 0; d < 16; ++d) {
                float4 k4 = kr[d];
                sj = fmaf(q4[d].x, k4.x, sj);
                sj = fmaf(q4[d].y, k4.y, sj);
                sj = fmaf(q4[d].z, k4.z, sj);
                sj = fmaf(q4[d].w, k4.w, sj);
            }
            sj *= 0.125f;
            sj = (kbase + j <= qg) ? sj : -1e30f;
            s[j] = sj;
            tmax = fmaxf(tmax, sj);
        }

        float mnew = fmaxf(mi, tmax);
        float corr = __expf(mi - mnew);
        l *= corr;
#pragma unroll
        for (int d = 0; d < 16; ++d) {
            o4[d].x *= corr; o4[d].y *= corr; o4[d].z *= corr; o4[d].w *= corr;
        }
#pragma unroll 4
        for (int j = 0; j < KT; ++j) {
            float p = __expf(s[j] - mnew);
            l += p;
            const float4* vr = (const float4*)Vs[j];
#pragma unroll
            for (int d = 0; d < 16; ++d) {
                float4 v4 = vr[d];
                o4[d].x = fmaf(p, v4.x, o4[d].x);
                o4[d].y = fmaf(p, v4.y, o4[d].y);
                o4[d].z = fmaf(p, v4.z, o4[d].z);
                o4[d].w = fmaf(p, v4.w, o4[d].w);
            }
        }
        mi = mnew;
        __syncthreads();
    }

    float inv = 1.f / l;
    float4* op = (float4*)(Og + ((size_t)(b * Sn + qg)) * En + h * Dn);
#pragma unroll
    for (int i = 0; i < 16; ++i) {
        float4 v = o4[i];
        v.x *= inv; v.y *= inv; v.z *= inv; v.w *= inv;
        op[i] = v;
    }
}

// ---------------------------------------------------------------------------
// Final head
// ---------------------------------------------------------------------------
__global__ void head_kernel(const float* __restrict__ X,
                            const float* __restrict__ Wout,
                            const float* __restrict__ bout,
                            float* __restrict__ out) {
    int gw = (blockIdx.x * blockDim.x + threadIdx.x) >> 5;
    int lane = threadIdx.x & 31;
    if (gw >= Mn) return;
    const float4* xr = (const float4*)(X + (size_t)gw * En);
    const float4* w4 = (const float4*)Wout;
    float acc = 0.f;
#pragma unroll
    for (int i = 0; i < 4; ++i) {
        float4 xv = xr[lane + i * 32];
        float4 wv = w4[lane + i * 32];
        acc += xv.x * wv.x + xv.y * wv.y + xv.z * wv.z + xv.w * wv.w;
    }
#pragma unroll
    for (int o = 16; o > 0; o >>= 1)
        acc += __shfl_xor_sync(0xffffffffu, acc, o);
    if (lane == 0) out[gw] = acc + bout[0];
}

// ---------------------------------------------------------------------------
// Launch
// ---------------------------------------------------------------------------
extern "C" void kernel_launch(void* const* d_in, const int* in_sizes, int n_in,
                              void* d_out, int out_size) {
    const int*   tok   = (const int*)d_in[0];
    const float* table = (const float*)d_in[1];
    const float* Wq    = (const float*)d_in[2];
    const float* bq    = (const float*)d_in[3];
    const float* Wk    = (const float*)d_in[4];
    const float* bk    = (const float*)d_in[5];
    const float* Wv    = (const float*)d_in[6];
    const float* bv    = (const float*)d_in[7];
    const float* Wo    = (const float*)d_in[8];
    const float* bo    = (const float*)d_in[9];
    const float* Wout  = (const float*)d_in[10];
    const float* bout  = (const float*)d_in[11];
    float* out = (float*)d_out;

    void* base = nullptr;
    cudaGetSymbolAddress(&base, g_buf);
    float* X   = (float*)base;
    float* Qb  = X + ME;
    float* Kb  = X + 2 * ME;
    float* Vb  = X + 3 * ME;
    float* Ab  = X + 4 * ME;
    float* PE  = X + 5 * ME;
    float* WT  = PE + (size_t)Sn * En;
    float* WTq = WT;
    float* WTk = WT + Ln * WSZ;
    float* WTv = WT + 2 * Ln * WSZ;
    float* WTo = WT + 3 * Ln * WSZ;

    static bool attr_done = false;
    if (!attr_done) {
        cudaFuncSetAttribute(gemm_mma<false>, cudaFuncAttributeMaxDynamicSharedMemorySize, SMEM_GEMM);
        cudaFuncSetAttribute(gemm_mma<true>,  cudaFuncAttributeMaxDynamicSharedMemorySize, SMEM_GEMM);
        attr_done = true;
    }

    pe_kernel<<<(Sn * En + 255) / 256, 256>>>(PE);
    embed_kernel<<<(Mn * (En / 4) + 255) / 256, 256>>>(tok, table, PE, X);

    dim3 tg(16, 16, Ln);
    dim3 tb2(32, 8);
    transpose512<<<tg, tb2>>>(Wq, WTq);
    transpose512<<<tg, tb2>>>(Wk, WTk);
    transpose512<<<tg, tb2>>>(Wv, WTv);
    transpose512<<<tg, tb2>>>(Wo, WTo);

    dim3 gg(En / 128, Mn / 128);   // (4, 256)
    dim3 ag(Sn / 128, Hn, Bn);
    for (int l = 0; l < Ln; ++l) {
        gemm_mma<false><<<gg, 256, SMEM_GEMM>>>(X,  WTq + (size_t)l * WSZ, bq + l * En, nullptr, Qb);
        gemm_mma<false><<<gg, 256, SMEM_GEMM>>>(X,  WTk + (size_t)l * WSZ, bk + l * En, nullptr, Kb);
        gemm_mma<false><<<gg, 256, SMEM_GEMM>>>(X,  WTv + (size_t)l * WSZ, bv + l * En, nullptr, Vb);
        attn_kernel<<<ag, 128>>>(Qb, Kb, Vb, Ab);
        gemm_mma<true><<<gg, 256, SMEM_GEMM>>>(Ab, WTo + (size_t)l * WSZ, bo + l * En, X, X);
    }
    head_kernel<<<(Mn * 32 + 255) / 256, 256>>>(X, Wout, bout, out);
}

// round 4
// speedup vs baseline: 1.1029x; 1.1029x over previous
#include <cuda_runtime.h>
#include <cstdint>
#include <math.h>

// ---------------------------------------------------------------------------
// Problem constants
// ---------------------------------------------------------------------------
static constexpr int Bn = 32;
static constexpr int Sn = 1024;
static constexpr int En = 512;
static constexpr int Hn = 8;
static constexpr int Dn = 64;       // E / H
static constexpr int Ln = 2;
static constexpr int Mn = Bn * Sn;  // 32768 rows
static constexpr size_t ME = (size_t)Mn * En;  // 16,777,216 elements

// Scratch arena: X, Q, K, V, Attn (5 * 64MB) + PE table (2MB)
__device__ float g_buf[5 * ME + (size_t)Sn * En];

// ---------------------------------------------------------------------------
// Packed f32x2 helpers (Blackwell FFMA2 pipe, PTX-only)
// ---------------------------------------------------------------------------
__device__ __forceinline__ uint64_t pack2(float lo, float hi) {
    uint64_t r;
    asm("mov.b64 %0, {%1, %2};" : "=l"(r) : "f"(lo), "f"(hi));
    return r;
}
__device__ __forceinline__ void fma2(uint64_t& d, uint64_t a, uint64_t b) {
    asm("fma.rn.f32x2 %0, %1, %2, %0;" : "+l"(d) : "l"(a), "l"(b));
}
__device__ __forceinline__ void mul2(uint64_t& d, uint64_t a, uint64_t b) {
    asm("mul.rn.f32x2 %0, %1, %2;" : "=l"(d) : "l"(a), "l"(b));
}
__device__ __forceinline__ float2 unpack2(uint64_t v) {
    float2 f;
    asm("mov.b64 {%0, %1}, %2;" : "=f"(f.x), "=f"(f.y) : "l"(v));
    return f;
}

// ---------------------------------------------------------------------------
// Positional encoding table
// ---------------------------------------------------------------------------
__global__ void pe_kernel(float* __restrict__ pe) {
    int idx = blockIdx.x * blockDim.x + threadIdx.x;
    if (idx >= Sn * En) return;
    int s = idx >> 9;
    int e = idx & 511;
    float i2 = (float)(e & ~1);
    float div = __expf(i2 * (-9.210340371976184f / (float)En));
    float a = (float)s * div;
    pe[idx] = (e & 1) ? cosf(a) : sinf(a);
}

// ---------------------------------------------------------------------------
// Embedding gather + PE add
// ---------------------------------------------------------------------------
__global__ void embed_kernel(const int* __restrict__ tok,
                             const float* __restrict__ table,
                             const float* __restrict__ pe,
                             float* __restrict__ x) {
    int idx4 = blockIdx.x * blockDim.x + threadIdx.x;
    if (idx4 >= Mn * (En / 4)) return;
    int row = idx4 >> 7;
    int d4  = idx4 & 127;
    int s   = row & (Sn - 1);
    int t   = tok[row];
    float4 tv = ((const float4*)table)[(size_t)t * 128 + d4];
    float4 pv = ((const float4*)pe)[(size_t)s * 128 + d4];
    float4 o;
    o.x = tv.x + pv.x; o.y = tv.y + pv.y; o.z = tv.z + pv.z; o.w = tv.w + pv.w;
    ((float4*)x)[idx4] = o;
}

// ---------------------------------------------------------------------------
// SGEMM with FFMA2: C[M,512] = A[M,512] @ W[512,512] (+ bias / relu+res)
// 128x128x16 tile, 256 threads, 8x8 microtile (as 8x4 packed pairs).
// ---------------------------------------------------------------------------
template <bool RELU_RES>
__global__ __launch_bounds__(256, 2)
void gemm512(const float* __restrict__ A, const float* __restrict__ W,
             const float* __restrict__ bias, const float* __restrict__ res,
             float* __restrict__ C) {
    __shared__ float As[16][128];
    __shared__ float Bs[16][128];
    const int tid = threadIdx.x;
    const int tx = tid & 15;
    const int ty = tid >> 4;
    const int row0 = blockIdx.y * 128;
    const int col0 = blockIdx.x * 128;

    uint64_t acc2[8][4];   // pairs of columns
    const uint64_t z2 = 0ull;
#pragma unroll
    for (int i = 0; i < 8; ++i)
#pragma unroll
        for (int j = 0; j < 4; ++j) acc2[i][j] = z2;

    for (int k0 = 0; k0 < En; k0 += 16) {
        // load A tile 128x16 (transposed into As[k][m])
#pragma unroll
        for (int i = 0; i < 2; ++i) {
            int idx = tid + i * 256;
            int m  = idx >> 2;
            int kk = (idx & 3) << 2;
            float4 a = *(const float4*)&A[(size_t)(row0 + m) * En + k0 + kk];
            As[kk + 0][m] = a.x; As[kk + 1][m] = a.y;
            As[kk + 2][m] = a.z; As[kk + 3][m] = a.w;
        }
        // load B tile 16x128
#pragma unroll
        for (int i = 0; i < 2; ++i) {
            int idx = tid + i * 256;
            int kk = idx >> 5;
            int n4 = idx & 31;
            *(float4*)&Bs[kk][n4 << 2] =
                *(const float4*)&W[(size_t)(k0 + kk) * En + col0 + (n4 << 2)];
        }
        __syncthreads();
#pragma unroll
        for (int kk = 0; kk < 16; ++kk) {
            float a[8];
            *(float4*)&a[0] = *(const float4*)&As[kk][ty * 8];
            *(float4*)&a[4] = *(const float4*)&As[kk][ty * 8 + 4];
            ulonglong2 b01 = *(const ulonglong2*)&Bs[kk][tx * 4];       // cols tx*4..+3
            ulonglong2 b23 = *(const ulonglong2*)&Bs[kk][64 + tx * 4];  // cols 64+tx*4..+3
#pragma unroll
            for (int i = 0; i < 8; ++i) {
                uint64_t av = pack2(a[i], a[i]);
                fma2(acc2[i][0], av, b01.x);
                fma2(acc2[i][1], av, b01.y);
                fma2(acc2[i][2], av, b23.x);
                fma2(acc2[i][3], av, b23.y);
            }
        }
        __syncthreads();
    }

    // epilogue
    float4 bi0 = *(const float4*)&bias[col0 + tx * 4];
    float4 bi1 = *(const float4*)&bias[col0 + 64 + tx * 4];
#pragma unroll
    for (int i = 0; i < 8; ++i) {
        int m = row0 + ty * 8 + i;
        size_t off0 = (size_t)m * En + col0 + tx * 4;
        size_t off1 = off0 + 64;
        float2 p0 = unpack2(acc2[i][0]);
        float2 p1 = unpack2(acc2[i][1]);
        float2 p2 = unpack2(acc2[i][2]);
        float2 p3 = unpack2(acc2[i][3]);
        float4 v0, v1;
        v0.x = p0.x + bi0.x; v0.y = p0.y + bi0.y;
        v0.z = p1.x + bi0.z; v0.w = p1.y + bi0.w;
        v1.x = p2.x + bi1.x; v1.y = p2.y + bi1.y;
        v1.z = p3.x + bi1.z; v1.w = p3.y + bi1.w;
        if (RELU_RES) {
            float4 r0 = *(const float4*)&res[off0];
            float4 r1 = *(const float4*)&res[off1];
            v0.x = r0.x + fmaxf(v0.x, 0.f); v0.y = r0.y + fmaxf(v0.y, 0.f);
            v0.z = r0.z + fmaxf(v0.z, 0.f); v0.w = r0.w + fmaxf(v0.w, 0.f);
            v1.x = r1.x + fmaxf(v1.x, 0.f); v1.y = r1.y + fmaxf(v1.y, 0.f);
            v1.z = r1.z + fmaxf(v1.z, 0.f); v1.w = r1.w + fmaxf(v1.w, 0.f);
        }
        *(float4*)&C[off0] = v0;
        *(float4*)&C[off1] = v1;
    }
}

// ---------------------------------------------------------------------------
// Causal flash attention with FFMA2. One thread = one query row.
// q, o held as 32 packed f32x2 regs each. K/V staged in 32-row smem tiles.
// ---------------------------------------------------------------------------
static constexpr int KT = 32;

__global__ __launch_bounds__(128)
void attn_kernel(const float* __restrict__ Q, const float* __restrict__ Kg,
                 const float* __restrict__ Vg, float* __restrict__ Og) {
    __shared__ float Ks[KT][64];
    __shared__ float Vs[KT][64];
    const int b = blockIdx.z, h = blockIdx.y, qt = blockIdx.x;
    const int r = threadIdx.x;
    const int qg = qt * 128 + r;

    const ulonglong2* qp = (const ulonglong2*)(Q + ((size_t)(b * Sn + qg)) * En + h * Dn);
    uint64_t q2[32];
#pragma unroll
    for (int i = 0; i < 16; ++i) {
        ulonglong2 t = qp[i];
        q2[2 * i] = t.x; q2[2 * i + 1] = t.y;
    }
    uint64_t o2[32];
#pragma unroll
    for (int i = 0; i < 32; ++i) o2[i] = 0ull;

    float mi = -1e30f, l = 0.f;
    const int nkt = qt * 4 + 4;  // key tiles up to & including the diagonal

    for (int kt = 0; kt < nkt; ++kt) {
        size_t base = ((size_t)(b * Sn + kt * KT)) * En + h * Dn;
#pragma unroll
        for (int i = 0; i < 4; ++i) {
            int idx = r + i * 128;
            int j  = idx >> 4;
            int d4 = idx & 15;
            ((float4*)Ks[j])[d4] = *(const float4*)(Kg + base + (size_t)j * En + d4 * 4);
            ((float4*)Vs[j])[d4] = *(const float4*)(Vg + base + (size_t)j * En + d4 * 4);
        }
        __syncthreads();

        float s[KT];                         // local-mem, L1-resident
        float tmax = -1e30f;
        const int kbase = kt * KT;
#pragma unroll 4
        for (int j = 0; j < KT; ++j) {
            const ulonglong2* kr = (const ulonglong2*)Ks[j];
            uint64_t sa = 0ull, sb = 0ull;   // two chains for ILP
#pragma unroll
            for (int d = 0; d < 16; ++d) {
                ulonglong2 kv = kr[d];
                fma2(sa, q2[2 * d], kv.x);
                fma2(sb, q2[2 * d + 1], kv.y);
            }
            float2 fa = unpack2(sa), fb = unpack2(sb);
            float sj = (fa.x + fa.y) + (fb.x + fb.y);
            sj *= 0.125f;                              // 1/sqrt(64)
            sj = (kbase + j <= qg) ? sj : -1e30f;      // causal mask
            s[j] = sj;
            tmax = fmaxf(tmax, sj);
        }

        float mnew = fmaxf(mi, tmax);
        float corr = __expf(mi - mnew);
        l *= corr;
        uint64_t c2 = pack2(corr, corr);
#pragma unroll
        for (int d = 0; d < 32; ++d) mul2(o2[d], o2[d], c2);
#pragma unroll 4
        for (int j = 0; j < KT; ++j) {
            float p = __expf(s[j] - mnew);
            l += p;
            uint64_t p2 = pack2(p, p);
            const ulonglong2* vr = (const ulonglong2*)Vs[j];
#pragma unroll
            for (int d = 0; d < 16; ++d) {
                ulonglong2 vv = vr[d];
                fma2(o2[2 * d],     p2, vv.x);
                fma2(o2[2 * d + 1], p2, vv.y);
            }
        }
        mi = mnew;
        __syncthreads();
    }

    float inv = 1.f / l;
    float4* op = (float4*)(Og + ((size_t)(b * Sn + qg)) * En + h * Dn);
#pragma unroll
    for (int i = 0; i < 16; ++i) {
        float2 lo = unpack2(o2[2 * i]);
        float2 hi = unpack2(o2[2 * i + 1]);
        float4 v;
        v.x = lo.x * inv; v.y = lo.y * inv;
        v.z = hi.x * inv; v.w = hi.y * inv;
        op[i] = v;
    }
}

// ---------------------------------------------------------------------------
// Final head: out[m] = X[m,:] . W_out[:,0] + b_out   (warp per row)
// ---------------------------------------------------------------------------
__global__ void head_kernel(const float* __restrict__ X,
                            const float* __restrict__ Wout,
                            const float* __restrict__ bout,
                            float* __restrict__ out) {
    int gw = (blockIdx.x * blockDim.x + threadIdx.x) >> 5;
    int lane = threadIdx.x & 31;
    if (gw >= Mn) return;
    const float4* xr = (const float4*)(X + (size_t)gw * En);
    const float4* w4 = (const float4*)Wout;
    float acc = 0.f;
#pragma unroll
    for (int i = 0; i < 4; ++i) {
        float4 xv = xr[lane + i * 32];
        float4 wv = w4[lane + i * 32];
        acc += xv.x * wv.x + xv.y * wv.y + xv.z * wv.z + xv.w * wv.w;
    }
#pragma unroll
    for (int o = 16; o > 0; o >>= 1)
        acc += __shfl_xor_sync(0xffffffffu, acc, o);
    if (lane == 0) out[gw] = acc + bout[0];
}

// ---------------------------------------------------------------------------
// Launch
// ---------------------------------------------------------------------------
extern "C" void kernel_launch(void* const* d_in, const int* in_sizes, int n_in,
                              void* d_out, int out_size) {
    const int*   tok   = (const int*)d_in[0];
    const float* table = (const float*)d_in[1];
    const float* Wq    = (const float*)d_in[2];
    const float* bq    = (const float*)d_in[3];
    const float* Wk    = (const float*)d_in[4];
    const float* bk    = (const float*)d_in[5];
    const float* Wv    = (const float*)d_in[6];
    const float* bv    = (const float*)d_in[7];
    const float* Wo    = (const float*)d_in[8];
    const float* bo    = (const float*)d_in[9];
    const float* Wout  = (const float*)d_in[10];
    const float* bout  = (const float*)d_in[11];
    float* out = (float*)d_out;

    void* base = nullptr;
    cudaGetSymbolAddress(&base, g_buf);   // not a stream op: capture-safe
    float* X  = (float*)base;
    float* Qb = X + ME;
    float* Kb = X + 2 * ME;
    float* Vb = X + 3 * ME;
    float* Ab = X + 4 * ME;
    float* PE = X + 5 * ME;

    pe_kernel<<<(Sn * En + 255) / 256, 256>>>(PE);
    embed_kernel<<<(Mn * (En / 4) + 255) / 256, 256>>>(tok, table, PE, X);

    dim3 gg(En / 128, Mn / 128);   // (4, 256)
    dim3 ag(Sn / 128, Hn, Bn);     // (8, 8, 32)
    for (int l = 0; l < Ln; ++l) {
        const float* wq = Wq + (size_t)l * En * En; const float* bql = bq + l * En;
        const float* wk = Wk + (size_t)l * En * En; const float* bkl = bk + l * En;
        const float* wv = Wv + (size_t)l * En * En; const float* bvl = bv + l * En;
        const float* wo = Wo + (size_t)l * En * En; const float* bol = bo + l * En;
        gemm512<false><<<gg, 256>>>(X,  wq, bql, nullptr, Qb);
        gemm512<false><<<gg, 256>>>(X,  wk, bkl, nullptr, Kb);
        gemm512<false><<<gg, 256>>>(X,  wv, bvl, nullptr, Vb);
        attn_kernel<<<ag, 128>>>(Qb, Kb, Vb, Ab);
        gemm512<true><<<gg, 256>>>(Ab, wo, bol, X, X);   // X = X + relu(attn@Wo+bo)
    }
    head_kernel<<<(Mn * 32 + 255) / 256, 256>>>(X, Wout, bout, out);
}

// round 5
// speedup vs baseline: 1.3008x; 1.1794x over previous
#include <cuda_runtime.h>
#include <cstdint>
#include <math.h>

// ---------------------------------------------------------------------------
// Problem constants
// ---------------------------------------------------------------------------
static constexpr int Bn = 32;
static constexpr int Sn = 1024;
static constexpr int En = 512;
static constexpr int Hn = 8;
static constexpr int Dn = 64;       // E / H
static constexpr int Ln = 2;
static constexpr int Mn = Bn * Sn;  // 32768 rows
static constexpr size_t ME = (size_t)Mn * En;  // 16,777,216 elements

// Scratch arena: X, Q, K, V, Attn (5 * 64MB) + PE table (2MB)
__device__ float g_buf[5 * ME + (size_t)Sn * En];

// ---------------------------------------------------------------------------
// Helpers
// ---------------------------------------------------------------------------
__device__ __forceinline__ uint64_t pack2(float lo, float hi) {
    uint64_t r;
    asm("mov.b64 %0, {%1, %2};" : "=l"(r) : "f"(lo), "f"(hi));
    return r;
}
__device__ __forceinline__ void fma2(uint64_t& d, uint64_t a, uint64_t b) {
    asm("fma.rn.f32x2 %0, %1, %2, %0;" : "+l"(d) : "l"(a), "l"(b));
}
__device__ __forceinline__ void mul2(uint64_t& d, uint64_t a, uint64_t b) {
    asm("mul.rn.f32x2 %0, %1, %2;" : "=l"(d) : "l"(a), "l"(b));
}
__device__ __forceinline__ float2 unpack2(uint64_t v) {
    float2 f;
    asm("mov.b64 {%0, %1}, %2;" : "=f"(f.x), "=f"(f.y) : "l"(v));
    return f;
}
__device__ __forceinline__ uint32_t smem_u32(const void* p) {
    uint32_t a;
    asm("{ .reg .u64 t; cvta.to.shared.u64 t, %1; cvt.u32.u64 %0, t; }" : "=r"(a) : "l"(p));
    return a;
}
__device__ __forceinline__ void cp16(uint32_t s, const void* g) {
    asm volatile("cp.async.cg.shared.global [%0], [%1], 16;" :: "r"(s), "l"(g));
}
__device__ __forceinline__ void cp_commit() {
    asm volatile("cp.async.commit_group;");
}
__device__ __forceinline__ void cp_wait_all() {
    asm volatile("cp.async.wait_group 0;");
}

// ---------------------------------------------------------------------------
// Positional encoding table
// ---------------------------------------------------------------------------
__global__ void pe_kernel(float* __restrict__ pe) {
    int idx = blockIdx.x * blockDim.x + threadIdx.x;
    if (idx >= Sn * En) return;
    int s = idx >> 9;
    int e = idx & 511;
    float i2 = (float)(e & ~1);
    float div = __expf(i2 * (-9.210340371976184f / (float)En));
    float a = (float)s * div;
    pe[idx] = (e & 1) ? cosf(a) : sinf(a);
}

// ---------------------------------------------------------------------------
// Embedding gather + PE add
// ---------------------------------------------------------------------------
__global__ void embed_kernel(const int* __restrict__ tok,
                             const float* __restrict__ table,
                             const float* __restrict__ pe,
                             float* __restrict__ x) {
    int idx4 = blockIdx.x * blockDim.x + threadIdx.x;
    if (idx4 >= Mn * (En / 4)) return;
    int row = idx4 >> 7;
    int d4  = idx4 & 127;
    int s   = row & (Sn - 1);
    int t   = tok[row];
    float4 tv = ((const float4*)table)[(size_t)t * 128 + d4];
    float4 pv = ((const float4*)pe)[(size_t)s * 128 + d4];
    float4 o;
    o.x = tv.x + pv.x; o.y = tv.y + pv.y; o.z = tv.z + pv.z; o.w = tv.w + pv.w;
    ((float4*)x)[idx4] = o;
}

// ---------------------------------------------------------------------------
// SGEMM v3: cp.async double-buffered, FFMA2 inner, 1 sync per K-chunk.
// C[M,512] = A[M,512] @ W[512,512] (+bias / relu+res).
// Tile 128x128, 256 threads, 8x8 microtile (4 col-pairs).
// As m-major [128][16] (cp.async-friendly; a reads are broadcast LDS.32).
// Bs k-major [16][128] (native row copy from W).
// ---------------------------------------------------------------------------
template <bool RELU_RES>
__global__ __launch_bounds__(256, 2)
void gemm512(const float* __restrict__ A, const float* __restrict__ W,
             const float* __restrict__ bias, const float* __restrict__ res,
             float* __restrict__ C) {
    __shared__ float As[2][128 * 16];
    __shared__ float Bs[2][16 * 128];
    const int tid = threadIdx.x;
    const int tx = tid & 15;
    const int ty = tid >> 4;
    const int row0 = blockIdx.y * 128;
    const int col0 = blockIdx.x * 128;
    const uint32_t aS = smem_u32(As[0]);
    const uint32_t bS = smem_u32(Bs[0]);

    uint64_t acc2[8][4];
#pragma unroll
    for (int i = 0; i < 8; ++i)
#pragma unroll
        for (int j = 0; j < 4; ++j) acc2[i][j] = 0ull;

    auto issue = [&](int c) {
        const int buf = c & 1;
        const uint32_t ab = aS + buf * (128 * 16 * 4);
        const uint32_t bb = bS + buf * (16 * 128 * 4);
        const float* Ag = A + (size_t)row0 * En + c * 16;
        const float* Wg = W + (size_t)(c * 16) * En + col0;
#pragma unroll
        for (int i = 0; i < 2; ++i) {                 // A: 512 cp16
            int idx = tid + i * 256;
            int m = idx >> 2, k4 = idx & 3;
            cp16(ab + (m * 16 + k4 * 4) * 4, Ag + (size_t)m * En + k4 * 4);
        }
#pragma unroll
        for (int i = 0; i < 2; ++i) {                 // B: 512 cp16
            int idx = tid + i * 256;
            int kk = idx >> 5, n4 = idx & 31;
            cp16(bb + (kk * 128 + n4 * 4) * 4, Wg + (size_t)kk * En + n4 * 4);
        }
        cp_commit();
    };

    issue(0);
    for (int c = 0; c < 32; ++c) {
        cp_wait_all();
        __syncthreads();
        if (c < 31) issue(c + 1);                     // overlaps compute below
        const float* as_ = As[c & 1];
        const float* bs_ = Bs[c & 1];
#pragma unroll
        for (int kk = 0; kk < 16; ++kk) {
            ulonglong2 b01 = *(const ulonglong2*)&bs_[kk * 128 + tx * 4];
            ulonglong2 b23 = *(const ulonglong2*)&bs_[kk * 128 + 64 + tx * 4];
#pragma unroll
            for (int i = 0; i < 8; ++i) {
                float a = as_[(ty * 8 + i) * 16 + kk];   // broadcast LDS.32
                uint64_t av = pack2(a, a);
                fma2(acc2[i][0], av, b01.x);
                fma2(acc2[i][1], av, b01.y);
                fma2(acc2[i][2], av, b23.x);
                fma2(acc2[i][3], av, b23.y);
            }
        }
    }

    // epilogue
    float4 bi0 = *(const float4*)&bias[col0 + tx * 4];
    float4 bi1 = *(const float4*)&bias[col0 + 64 + tx * 4];
#pragma unroll
    for (int i = 0; i < 8; ++i) {
        int m = row0 + ty * 8 + i;
        size_t off0 = (size_t)m * En + col0 + tx * 4;
        size_t off1 = off0 + 64;
        float2 p0 = unpack2(acc2[i][0]);
        float2 p1 = unpack2(acc2[i][1]);
        float2 p2 = unpack2(acc2[i][2]);
        float2 p3 = unpack2(acc2[i][3]);
        float4 v0, v1;
        v0.x = p0.x + bi0.x; v0.y = p0.y + bi0.y;
        v0.z = p1.x + bi0.z; v0.w = p1.y + bi0.w;
        v1.x = p2.x + bi1.x; v1.y = p2.y + bi1.y;
        v1.z = p3.x + bi1.z; v1.w = p3.y + bi1.w;
        if (RELU_RES) {
            float4 r0 = *(const float4*)&res[off0];
            float4 r1 = *(const float4*)&res[off1];
            v0.x = r0.x + fmaxf(v0.x, 0.f); v0.y = r0.y + fmaxf(v0.y, 0.f);
            v0.z = r0.z + fmaxf(v0.z, 0.f); v0.w = r0.w + fmaxf(v0.w, 0.f);
            v1.x = r1.x + fmaxf(v1.x, 0.f); v1.y = r1.y + fmaxf(v1.y, 0.f);
            v1.z = r1.z + fmaxf(v1.z, 0.f); v1.w = r1.w + fmaxf(v1.w, 0.f);
        }
        *(float4*)&C[off0] = v0;
        *(float4*)&C[off1] = v1;
    }
}

// ---------------------------------------------------------------------------
// Causal flash attention v2: KT=64, cp.async double-buffered K/V tiles,
// one __syncthreads per tile, exp2-domain softmax, FFMA2 math.
// One thread = one query row. Block = 128 q rows of one (b,h).
// Dynamic smem: 2 bufs x (64x64 K + 64x64 V) floats = 64 KB.
// ---------------------------------------------------------------------------
static constexpr int KT = 64;
static constexpr int ATT_SMEM = 2 * 2 * KT * Dn * (int)sizeof(float);  // 65536
static constexpr float SC2 = 0.18033688011112042f;  // (1/8) * log2(e)

__global__ __launch_bounds__(128)
void attn_kernel(const float* __restrict__ Q, const float* __restrict__ Kg,
                 const float* __restrict__ Vg, float* __restrict__ Og) {
    extern __shared__ float smA[];   // [buf][K(4096) | V(4096)]
    const uint32_t sS = smem_u32(smA);
    const int b = blockIdx.z, h = blockIdx.y, qt = blockIdx.x;
    const int r = threadIdx.x;
    const int qg = qt * 128 + r;

    const ulonglong2* qp = (const ulonglong2*)(Q + ((size_t)(b * Sn + qg)) * En + h * Dn);
    uint64_t q2[32];
#pragma unroll
    for (int i = 0; i < 16; ++i) {
        ulonglong2 t = qp[i];
        q2[2 * i] = t.x; q2[2 * i + 1] = t.y;
    }
    uint64_t o2[32];
#pragma unroll
    for (int i = 0; i < 32; ++i) o2[i] = 0ull;

    float mi = -1e30f, l = 0.f;
    const int nkt = qt * 2 + 2;      // 64-key tiles up to & incl. diagonal

    auto issue_tile = [&](int kt) {
        size_t base = ((size_t)(b * Sn + kt * KT)) * En + h * Dn;
        uint32_t kd = sS + (kt & 1) * 32768;
        uint32_t vd = kd + 16384;
#pragma unroll
        for (int i = 0; i < 8; ++i) {           // 1024 cp16 each for K and V
            int idx = r + i * 128;
            int row = idx >> 4, d4 = idx & 15;
            const float* src = Kg + base + (size_t)row * En + d4 * 4;
            const float* srv = Vg + base + (size_t)row * En + d4 * 4;
            uint32_t off = (row * 64 + d4 * 4) * 4;
            cp16(kd + off, src);
            cp16(vd + off, srv);
        }
        cp_commit();
    };

    issue_tile(0);
    for (int kt = 0; kt < nkt; ++kt) {
        cp_wait_all();
        __syncthreads();
        if (kt + 1 < nkt) issue_tile(kt + 1);   // overlaps compute below

        const float* Ks = smA + (kt & 1) * 8192;
        const float* Vs = Ks + 4096;
        const bool masked = (kt >= qt * 2);     // only diagonal-straddling tiles
        const int kbase = kt * KT;

        float s[KT];
        float tmax = -1e30f;
#pragma unroll 4
        for (int j = 0; j < KT; ++j) {
            const ulonglong2* kr = (const ulonglong2*)(Ks + j * 64);
            uint64_t sa = 0ull, sb = 0ull;
#pragma unroll
            for (int d = 0; d < 16; ++d) {
                ulonglong2 kv = kr[d];
                fma2(sa, q2[2 * d], kv.x);
                fma2(sb, q2[2 * d + 1], kv.y);
            }
            float2 fa = unpack2(sa), fb = unpack2(sb);
            float sj = ((fa.x + fa.y) + (fb.x + fb.y)) * SC2;   // exp2 domain
            if (masked && (kbase + j > qg)) sj = -1e30f;
            s[j] = sj;
            tmax = fmaxf(tmax, sj);
        }

        float mnew = fmaxf(mi, tmax);
        float corr = exp2f(mi - mnew);
        l *= corr;
        uint64_t c2 = pack2(corr, corr);
#pragma unroll
        for (int d = 0; d < 32; ++d) mul2(o2[d], o2[d], c2);
#pragma unroll 4
        for (int j = 0; j < KT; ++j) {
            float p = exp2f(s[j] - mnew);
            l += p;
            uint64_t p2 = pack2(p, p);
            const ulonglong2* vr = (const ulonglong2*)(Vs + j * 64);
#pragma unroll
            for (int d = 0; d < 16; ++d) {
                ulonglong2 vv = vr[d];
                fma2(o2[2 * d],     p2, vv.x);
                fma2(o2[2 * d + 1], p2, vv.y);
            }
        }
        mi = mnew;
    }

    float inv = 1.f / l;
    float4* op = (float4*)(Og + ((size_t)(b * Sn + qg)) * En + h * Dn);
#pragma unroll
    for (int i = 0; i < 16; ++i) {
        float2 lo = unpack2(o2[2 * i]);
        float2 hi = unpack2(o2[2 * i + 1]);
        float4 v;
        v.x = lo.x * inv; v.y = lo.y * inv;
        v.z = hi.x * inv; v.w = hi.y * inv;
        op[i] = v;
    }
}

// ---------------------------------------------------------------------------
// Final head: out[m] = X[m,:] . W_out[:,0] + b_out   (warp per row)
// ---------------------------------------------------------------------------
__global__ void head_kernel(const float* __restrict__ X,
                            const float* __restrict__ Wout,
                            const float* __restrict__ bout,
                            float* __restrict__ out) {
    int gw = (blockIdx.x * blockDim.x + threadIdx.x) >> 5;
    int lane = threadIdx.x & 31;
    if (gw >= Mn) return;
    const float4* xr = (const float4*)(X + (size_t)gw * En);
    const float4* w4 = (const float4*)Wout;
    float acc = 0.f;
#pragma unroll
    for (int i = 0; i < 4; ++i) {
        float4 xv = xr[lane + i * 32];
        float4 wv = w4[lane + i * 32];
        acc += xv.x * wv.x + xv.y * wv.y + xv.z * wv.z + xv.w * wv.w;
    }
#pragma unroll
    for (int o = 16; o > 0; o >>= 1)
        acc += __shfl_xor_sync(0xffffffffu, acc, o);
    if (lane == 0) out[gw] = acc + bout[0];
}

// ---------------------------------------------------------------------------
// Launch
// ---------------------------------------------------------------------------
extern "C" void kernel_launch(void* const* d_in, const int* in_sizes, int n_in,
                              void* d_out, int out_size) {
    const int*   tok   = (const int*)d_in[0];
    const float* table = (const float*)d_in[1];
    const float* Wq    = (const float*)d_in[2];
    const float* bq    = (const float*)d_in[3];
    const float* Wk    = (const float*)d_in[4];
    const float* bk    = (const float*)d_in[5];
    const float* Wv    = (const float*)d_in[6];
    const float* bv    = (const float*)d_in[7];
    const float* Wo    = (const float*)d_in[8];
    const float* bo    = (const float*)d_in[9];
    const float* Wout  = (const float*)d_in[10];
    const float* bout  = (const float*)d_in[11];
    float* out = (float*)d_out;

    void* base = nullptr;
    cudaGetSymbolAddress(&base, g_buf);   // not a stream op: capture-safe
    float* X  = (float*)base;
    float* Qb = X + ME;
    float* Kb = X + 2 * ME;
    float* Vb = X + 3 * ME;
    float* Ab = X + 4 * ME;
    float* PE = X + 5 * ME;

    static bool attr_done = false;
    if (!attr_done) {
        cudaFuncSetAttribute(attn_kernel, cudaFuncAttributeMaxDynamicSharedMemorySize, ATT_SMEM);
        attr_done = true;
    }

    pe_kernel<<<(Sn * En + 255) / 256, 256>>>(PE);
    embed_kernel<<<(Mn * (En / 4) + 255) / 256, 256>>>(tok, table, PE, X);

    dim3 gg(En / 128, Mn / 128);   // (4, 256)
    dim3 ag(Sn / 128, Hn, Bn);     // (8, 8, 32)
    for (int l = 0; l < Ln; ++l) {
        const float* wq = Wq + (size_t)l * En * En; const float* bql = bq + l * En;
        const float* wk = Wk + (size_t)l * En * En; const float* bkl = bk + l * En;
        const float* wv = Wv + (size_t)l * En * En; const float* bvl = bv + l * En;
        const float* wo = Wo + (size_t)l * En * En; const float* bol = bo + l * En;
        gemm512<false><<<gg, 256>>>(X,  wq, bql, nullptr, Qb);
        gemm512<false><<<gg, 256>>>(X,  wk, bkl, nullptr, Kb);
        gemm512<false><<<gg, 256>>>(X,  wv, bvl, nullptr, Vb);
        attn_kernel<<<ag, 128, ATT_SMEM>>>(Qb, Kb, Vb, Ab);
        gemm512<true><<<gg, 256>>>(Ab, wo, bol, X, X);   // X = X + relu(attn@Wo+bo)
    }
    head_kernel<<<(Mn * 32 + 255) / 256, 256>>>(X, Wout, bout, out);
}